// round 12
// baseline (speedup 1.0000x reference)
#include <cuda_runtime.h>
#include <cuda_bf16.h>
#include <math.h>
#include <cstdint>

#define B_    1024
#define D_    768
#define TD    1536
#define C_    150
#define CP    160
#define P_    64
#define K3    2304   // 3 * 768 packed bf16 K
#define USLAB 16     // u-GEMM k-split slabs

typedef unsigned long long u64;

#define PK2(d, lo, hi) asm("mov.b64 %0, {%1,%2};" : "=l"(d) : "f"(lo), "f"(hi))
#define UPK2(lo, hi, s) asm("mov.b64 {%0,%1}, %2;" : "=f"(lo), "=f"(hi) : "l"(s))
#define FMA2(d, a, b, c) asm("fma.rn.f32x2 %0, %1, %2, %3;" : "=l"(d) : "l"(a), "l"(b), "l"(c))
#define ADD2(d, a, b) asm("add.rn.f32x2 %0, %1, %2;" : "=l"(d) : "l"(a), "l"(b))

// ---------------- scratch (device globals; no allocation) ----------------
__device__ __align__(16) __nv_bfloat16 g_WxP[TD * K3];    // A-side: hi|hi|lo
__device__ __align__(16) __nv_bfloat16 g_WmP[TD * K3];
__device__ __align__(16) __nv_bfloat16 g_xP[B_ * K3];     // B-side: hi|lo|hi
__device__ __align__(16) __nv_bfloat16 g_memP[256 * K3];  // rows 150..255 zero
__device__ float g_xhT[TD * B_];              // xh transposed: [e][b] (+bias)
__device__ float g_mhT[TD * CP];              // [j][c], cols 150..159 zero
__device__ float g_seen_part[8][CP * B_];
__device__ float g_logits[CP * B_];
__device__ float g_u_part[USLAB][B_ * P_];
__device__ float g_u[B_ * P_];
__device__ float g_sqn[B_];
__device__ float g_pos_part[256];
__device__ float g_neg_part[256];
__device__ float g_cls_part[128];

// ---------------- small PTX helpers (all plain-sm_103-legal) ----------------
__device__ __forceinline__ uint32_t smem_u32(const void* p) {
    uint32_t a;
    asm("{ .reg .u64 t; cvta.to.shared.u64 t, %1; cvt.u32.u64 %0, t; }" : "=r"(a) : "l"(p));
    return a;
}
__device__ __forceinline__ void cp_async16(uint32_t sm, const void* g) {
    asm volatile("cp.async.cg.shared.global [%0], [%1], 16;" :: "r"(sm), "l"(g));
}
#define CP_COMMIT() asm volatile("cp.async.commit_group;")
#define CP_WAIT(n)  asm volatile("cp.async.wait_group %0;" :: "n"(n))
__device__ __forceinline__ void ldm4(uint32_t* r, uint32_t addr) {
    asm volatile("ldmatrix.sync.aligned.m8n8.x4.shared.b16 {%0,%1,%2,%3}, [%4];"
                 : "=r"(r[0]), "=r"(r[1]), "=r"(r[2]), "=r"(r[3]) : "r"(addr));
}
__device__ __forceinline__ void mma16816(float* c, const uint32_t* a, uint32_t b0, uint32_t b1) {
    asm volatile("mma.sync.aligned.m16n8k16.row.col.f32.bf16.bf16.f32 "
                 "{%0,%1,%2,%3}, {%4,%5,%6,%7}, {%8,%9}, {%0,%1,%2,%3};"
                 : "+f"(c[0]), "+f"(c[1]), "+f"(c[2]), "+f"(c[3])
                 : "r"(a[0]), "r"(a[1]), "r"(a[2]), "r"(a[3]), "r"(b0), "r"(b1));
}

// ---------------- fused hi/lo bf16 convert ----------------
__device__ __forceinline__ uint32_t pk_bf2(__nv_bfloat16 a, __nv_bfloat16 b) {
    __nv_bfloat162 t(a, b);
    return *reinterpret_cast<uint32_t*>(&t);
}
__device__ __forceinline__ void hilo4(float4 v, uint2& hi, uint2& lo) {
    __nv_bfloat16 h0 = __float2bfloat16(v.x), h1 = __float2bfloat16(v.y);
    __nv_bfloat16 h2 = __float2bfloat16(v.z), h3 = __float2bfloat16(v.w);
    __nv_bfloat16 l0 = __float2bfloat16(v.x - __bfloat162float(h0));
    __nv_bfloat16 l1 = __float2bfloat16(v.y - __bfloat162float(h1));
    __nv_bfloat16 l2 = __float2bfloat16(v.z - __bfloat162float(h2));
    __nv_bfloat16 l3 = __float2bfloat16(v.w - __bfloat162float(h3));
    hi.x = pk_bf2(h0, h1); hi.y = pk_bf2(h2, h3);
    lo.x = pk_bf2(l0, l1); lo.y = pk_bf2(l2, l3);
}
__global__ void conv_kernel(const float* __restrict__ x, const float* __restrict__ mem,
                            const float* __restrict__ fcw)
{
    const long NW = (long)TD * 192, NX = (long)B_ * 192, NM = 256L * 192;
    long gid = (long)blockIdx.x * 256 + threadIdx.x;
    if (gid < NW) {
        int r = (int)(gid / 192), k4 = (int)(gid % 192) * 4;
        float4 vx = *(const float4*)&fcw[(long)r * TD + k4];
        float4 vm = *(const float4*)&fcw[(long)r * TD + D_ + k4];
        uint2 hx, lx, hm, lm;
        hilo4(vx, hx, lx); hilo4(vm, hm, lm);
        *(uint2*)&g_WxP[(long)r * K3 + k4]            = hx;
        *(uint2*)&g_WxP[(long)r * K3 + D_ + k4]       = hx;
        *(uint2*)&g_WxP[(long)r * K3 + 2 * D_ + k4]   = lx;
        *(uint2*)&g_WmP[(long)r * K3 + k4]            = hm;
        *(uint2*)&g_WmP[(long)r * K3 + D_ + k4]       = hm;
        *(uint2*)&g_WmP[(long)r * K3 + 2 * D_ + k4]   = lm;
    } else if (gid < NW + NX) {
        long t = gid - NW;
        int r = (int)(t / 192), k4 = (int)(t % 192) * 4;
        float4 v = *(const float4*)&x[(long)r * D_ + k4];
        uint2 h, l; hilo4(v, h, l);
        *(uint2*)&g_xP[(long)r * K3 + k4]          = h;
        *(uint2*)&g_xP[(long)r * K3 + D_ + k4]     = l;
        *(uint2*)&g_xP[(long)r * K3 + 2 * D_ + k4] = h;
    } else if (gid < NW + NX + NM) {
        long t = gid - NW - NX;
        int r = (int)(t / 192), k4 = (int)(t % 192) * 4;
        uint2 h = make_uint2(0u, 0u), l = make_uint2(0u, 0u);
        if (r < C_) {
            float4 v = *(const float4*)&mem[(long)r * D_ + k4];
            hilo4(v, h, l);
        }
        *(uint2*)&g_memP[(long)r * K3 + k4]          = h;
        *(uint2*)&g_memP[(long)r * K3 + D_ + k4]     = l;
        *(uint2*)&g_memP[(long)r * K3 + 2 * D_ + k4] = h;
    }
}

// ---------------- mma.sync bf16 GEMM, 128x128 tile, cp.async double-buffered ----
#define ST_BYTES 36864
#define SMEM_MMA (2 * ST_BYTES)
#define PITCH    144

__global__ __launch_bounds__(256)
void gemm_mma(const float* __restrict__ fc_b)
{
    bool isX = (blockIdx.z == 0);
    if (!isX && blockIdx.x >= 2) return;
    extern __shared__ char smem[];
    const char* A  = (const char*)(isX ? g_WxP : g_WmP);
    const char* Bm = (const char*)(isX ? g_xP : g_memP);
    float* Out = isX ? g_xhT : g_mhT;
    int ldo = isX ? B_ : CP;
    int m0 = blockIdx.y * 128, n0 = blockIdx.x * 128;
    const long ROWB = (long)K3 * 2;

    int tid = threadIdx.x, lane = tid & 31, wid = tid >> 5;
    int wm = wid & 3, wn = wid >> 2;
    uint32_t sb = smem_u32(smem);

    float acc[2][8][4];
#pragma unroll
    for (int f = 0; f < 2; f++)
#pragma unroll
        for (int g = 0; g < 8; g++)
#pragma unroll
            for (int q = 0; q < 4; q++) acc[f][g][q] = 0.f;

    int lrow = tid >> 3, lc = (tid & 7) * 16;

#define STAGE_LOAD(ci, s) do { \
        uint32_t ao = sb + (s) * ST_BYTES, bo = ao + 18432; \
        long kb = (long)(ci) * 128; \
        cp_async16(ao + lrow * PITCH + lc,        A  + (long)(m0 + lrow) * ROWB + kb + lc); \
        cp_async16(ao + (lrow + 32) * PITCH + lc, A  + (long)(m0 + lrow + 32) * ROWB + kb + lc); \
        cp_async16(ao + (lrow + 64) * PITCH + lc, A  + (long)(m0 + lrow + 64) * ROWB + kb + lc); \
        cp_async16(ao + (lrow + 96) * PITCH + lc, A  + (long)(m0 + lrow + 96) * ROWB + kb + lc); \
        cp_async16(bo + lrow * PITCH + lc,        Bm + (long)(n0 + lrow) * ROWB + kb + lc); \
        cp_async16(bo + (lrow + 32) * PITCH + lc, Bm + (long)(n0 + lrow + 32) * ROWB + kb + lc); \
        cp_async16(bo + (lrow + 64) * PITCH + lc, Bm + (long)(n0 + lrow + 64) * ROWB + kb + lc); \
        cp_async16(bo + (lrow + 96) * PITCH + lc, Bm + (long)(n0 + lrow + 96) * ROWB + kb + lc); \
        CP_COMMIT(); \
    } while (0)

    STAGE_LOAD(0, 0);

    uint32_t aRow = (uint32_t)(wm * 32 + (lane & 15)) * PITCH + ((lane >> 4) & 1) * 16;
    uint32_t bRowBase = (uint32_t)(wn * 64 + (lane & 7)) * PITCH + (lane >> 3) * 16;

    for (int ci = 0; ci < 36; ci++) {
        int s = ci & 1;
        if (ci + 1 < 36) STAGE_LOAD(ci + 1, s ^ 1);
        if (ci + 1 < 36) CP_WAIT(1); else CP_WAIT(0);
        __syncthreads();
        uint32_t ao = sb + s * ST_BYTES, bo = ao + 18432;
#pragma unroll
        for (int h = 0; h < 2; h++) {
            uint32_t bfr[8][4];
#pragma unroll
            for (int g = 0; g < 8; g++)
                ldm4(bfr[g], bo + bRowBase + g * 8 * PITCH + h * 64);
#pragma unroll
            for (int ks = 0; ks < 2; ks++) {
                uint32_t afr[2][4];
#pragma unroll
                for (int f = 0; f < 2; f++)
                    ldm4(afr[f], ao + aRow + f * 16 * PITCH + h * 64 + ks * 32);
#pragma unroll
                for (int f = 0; f < 2; f++)
#pragma unroll
                    for (int g = 0; g < 8; g++)
                        mma16816(acc[f][g], afr[f], bfr[g][2 * ks], bfr[g][2 * ks + 1]);
            }
        }
        __syncthreads();
    }

    int gid = lane >> 2, tig = lane & 3;
#pragma unroll
    for (int f = 0; f < 2; f++) {
        int m = m0 + wm * 32 + f * 16 + gid;
        float b0 = isX ? fc_b[m] : 0.f;
        float b1 = isX ? fc_b[m + 8] : 0.f;
        float* r0 = Out + (long)m * ldo;
        float* r1 = Out + (long)(m + 8) * ldo;
#pragma unroll
        for (int g = 0; g < 8; g++) {
            int n = n0 + wn * 64 + g * 8 + 2 * tig;
            if (n < ldo) {
                *(float2*)&r0[n] = make_float2(acc[f][g][0] + b0, acc[f][g][1] + b0);
                *(float2*)&r1[n] = make_float2(acc[f][g][2] + b1, acc[f][g][3] + b1);
            }
        }
    }
}

// ================= fused stage A: seen (blocks 0..255) | u-GEMM (256..511) ====

__device__ __forceinline__ void seen_body(int bx, int by, char* buf,
                                          const float* __restrict__ xhT,
                                          const float* __restrict__ mhT,
                                          const float* __restrict__ p1w)
{
    float (*xs)[36]  = (float(*)[36])buf;            // 4608 B
    u64   (*ms2)[160] = (u64(*)[160])(buf + 4608);   // 40960 B
    float* ps = (float*)(buf + 45568);               // 128 B
    int tid = threadIdx.x;
    int tx = tid & 31, ty = tid >> 5;
    int bbase = bx * 32;
    int c0 = tx * 5;

    u64 acc0[5], acc1[5];
#pragma unroll
    for (int j = 0; j < 5; j++) { acc0[j] = 0ull; acc1[j] = 0ull; }

    for (int et = 0; et < 6; et++) {
        int eb = by * 192 + et * 32;
        {
            int el = tid >> 3, b4 = (tid & 7) * 4;
            *(float4*)&xs[el][b4] = *(const float4*)&xhT[(long)(eb + el) * B_ + bbase + b4];
        }
        {
            int el = tid >> 3, cf = (tid & 7) * 20;
#pragma unroll
            for (int q = 0; q < 5; q++) {
                float4 v = *(const float4*)&mhT[(long)(eb + el) * CP + cf + q * 4];
                PK2(ms2[el][cf + q * 4 + 0], v.x, v.x);
                PK2(ms2[el][cf + q * 4 + 1], v.y, v.y);
                PK2(ms2[el][cf + q * 4 + 2], v.z, v.z);
                PK2(ms2[el][cf + q * 4 + 3], v.w, v.w);
            }
        }
        if (tid < 8) *(float4*)&ps[tid * 4] = *(const float4*)&p1w[eb + tid * 4];
        __syncthreads();
#pragma unroll 4
        for (int ee = 0; ee < 32; ee++) {
            float p = ps[ee];
            u64 pp; PK2(pp, p, p);
            u64 x01 = *(u64*)&xs[ee][ty * 4];
            u64 x23 = *(u64*)&xs[ee][ty * 4 + 2];
#pragma unroll
            for (int j = 0; j < 5; j++) {
                u64 mm = ms2[ee][c0 + j];
                u64 t0, t1;
                ADD2(t0, x01, mm);
                ADD2(t1, x23, mm);
                float a, b, c, d;
                UPK2(a, b, t0); UPK2(c, d, t1);
                a = fmaxf(a, 0.f); b = fmaxf(b, 0.f);
                c = fmaxf(c, 0.f); d = fmaxf(d, 0.f);
                u64 r0, r1; PK2(r0, a, b); PK2(r1, c, d);
                FMA2(acc0[j], r0, pp, acc0[j]);
                FMA2(acc1[j], r1, pp, acc1[j]);
            }
        }
        __syncthreads();
    }
#pragma unroll
    for (int j = 0; j < 5; j++) {
        float v0, v1, v2, v3;
        UPK2(v0, v1, acc0[j]); UPK2(v2, v3, acc1[j]);
        *(float4*)&g_seen_part[by][(long)(c0 + j) * B_ + bbase + ty * 4] =
            make_float4(v0, v1, v2, v3);
    }
}

__device__ __forceinline__ void ugemm_body(int my, int mz, char* buf,
                                           const float* __restrict__ A,
                                           const float* __restrict__ Bm)
{
    float (*As)[68] = (float(*)[68])buf;             // 4352 B
    float (*Bs)[68] = (float(*)[68])(buf + 4352);    // 4352 B
    int tid = threadIdx.x;
    int tx = tid & 15, ty = tid >> 4;
    int m0 = my * 64;
    const int kc = TD / USLAB;
    int kb0 = mz * kc, kb1 = kb0 + kc;
    float* Out = &g_u_part[mz][0];

    float acc[4][4];
#pragma unroll
    for (int i = 0; i < 4; i++)
#pragma unroll
        for (int j = 0; j < 4; j++) acc[i][j] = 0.f;

    for (int kb = kb0; kb < kb1; kb += 16) {
        {
            int kl = tid >> 4, m4 = (tid & 15) * 4;
            float4 v = *(const float4*)&A[(long)(kb + kl) * B_ + m0 + m4];
            As[kl][m4 + 0] = fmaxf(v.x, 0.f);
            As[kl][m4 + 1] = fmaxf(v.y, 0.f);
            As[kl][m4 + 2] = fmaxf(v.z, 0.f);
            As[kl][m4 + 3] = fmaxf(v.w, 0.f);
        }
        {
            int nl = tid >> 2, k4 = (tid & 3) * 4;
            float4 v = *(const float4*)&Bm[(long)nl * TD + kb + k4];
            Bs[k4 + 0][nl] = v.x; Bs[k4 + 1][nl] = v.y;
            Bs[k4 + 2][nl] = v.z; Bs[k4 + 3][nl] = v.w;
        }
        __syncthreads();
#pragma unroll
        for (int kk = 0; kk < 16; kk++) {
            float4 a = *(float4*)&As[kk][ty * 4];
            float4 b = *(float4*)&Bs[kk][tx * 4];
            float av[4] = {a.x, a.y, a.z, a.w};
            float bv[4] = {b.x, b.y, b.z, b.w};
#pragma unroll
            for (int i = 0; i < 4; i++)
#pragma unroll
                for (int j = 0; j < 4; j++) acc[i][j] = fmaf(av[i], bv[j], acc[i][j]);
        }
        __syncthreads();
    }
#pragma unroll
    for (int i = 0; i < 4; i++) {
        int m = m0 + ty * 4 + i;
#pragma unroll
        for (int j = 0; j < 4; j++)
            Out[(long)m * P_ + tx * 4 + j] = acc[i][j];
    }
}

__global__ __launch_bounds__(256)
void fusedA(const float* __restrict__ xhT, const float* __restrict__ mhT,
            const float* __restrict__ p1w, const float* __restrict__ p2w)
{
    __shared__ __align__(16) char buf[45696];
    int blk = blockIdx.x;
    if (blk < 256) {
        seen_body(blk & 31, blk >> 5, buf, xhT, mhT, p1w);
    } else {
        int t = blk - 256;
        ugemm_body(t & 15, t >> 4, buf, xhT, p2w);
    }
}

// ============ fused stage B: logits (0..603) | u_norm (604..731) =============

__global__ __launch_bounds__(256)
void fusedB(const float* __restrict__ p1b, const float* __restrict__ p2b)
{
    int blk = blockIdx.x;
    if (blk < 604) {
        int idx = blk * 256 + threadIdx.x;
        if (idx >= (C_ + 1) * B_) return;
        float v = p1b[0];
#pragma unroll
        for (int s = 0; s < 8; s++) v += g_seen_part[s][idx];
        g_logits[idx] = v;
    } else {
        int wid = threadIdx.x >> 5, lane = threadIdx.x & 31;
        int b = (blk - 604) * 8 + wid;
        float v0 = p2b[lane], v1 = p2b[lane + 32];
#pragma unroll
        for (int s = 0; s < USLAB; s++) {
            v0 += g_u_part[s][b * P_ + lane];
            v1 += g_u_part[s][b * P_ + lane + 32];
        }
        float ss = v0 * v0 + v1 * v1;
#pragma unroll
        for (int o = 16; o > 0; o >>= 1) ss += __shfl_xor_sync(0xffffffffu, ss, o);
        float den = fmaxf(sqrtf(ss), 1e-12f);
        float w0 = v0 / den, w1 = v1 / den;
        g_u[b * P_ + lane] = w0;
        g_u[b * P_ + lane + 32] = w1;
        float s2 = w0 * w0 + w1 * w1;
#pragma unroll
        for (int o = 16; o > 0; o >>= 1) s2 += __shfl_xor_sync(0xffffffffu, s2, o);
        if (lane == 0) g_sqn[b] = s2;
    }
}

// ============ fused stage C: pair (0..255) | loss (256..383) =================

__device__ __forceinline__ void pair_body(int bx, int by, char* buf,
                                          const int* __restrict__ lb)
{
    float (*ui)[68] = (float(*)[68])buf;               // 17408
    float (*uj)[68] = (float(*)[68])(buf + 17408);     // 17408
    float* red = (float*)(buf + 34816);                // 1024
    float* sqi = (float*)(buf + 35840);                // 256
    float* sqj = (float*)(buf + 36096);                // 256
    int*   li  = (int*)  (buf + 36352);                // 256
    int*   lj  = (int*)  (buf + 36608);                // 256
    int tid = threadIdx.x;
    int tx = tid & 15, ty = tid >> 4;
    int i0 = by * 64, j0 = bx * 64;

#pragma unroll
    for (int t = 0; t < 4; t++) {
        int f4 = tid + t * 256;
        int r = f4 >> 4, k4 = (f4 & 15) * 4;
        *(float4*)&ui[r][k4] = *(const float4*)&g_u[(i0 + r) * P_ + k4];
        *(float4*)&uj[r][k4] = *(const float4*)&g_u[(j0 + r) * P_ + k4];
    }
    if (tid < 64) {
        sqi[tid] = g_sqn[i0 + tid]; sqj[tid] = g_sqn[j0 + tid];
        li[tid] = lb[i0 + tid];     lj[tid] = lb[j0 + tid];
    }
    __syncthreads();

    float acc[4][4];
#pragma unroll
    for (int i = 0; i < 4; i++)
#pragma unroll
        for (int j = 0; j < 4; j++) acc[i][j] = 0.f;

#pragma unroll
    for (int k4 = 0; k4 < 16; k4++) {
        float4 ai[4], aj[4];
#pragma unroll
        for (int i = 0; i < 4; i++) ai[i] = *(float4*)&ui[ty * 4 + i][k4 * 4];
#pragma unroll
        for (int j = 0; j < 4; j++) aj[j] = *(float4*)&uj[tx * 4 + j][k4 * 4];
#pragma unroll
        for (int i = 0; i < 4; i++)
#pragma unroll
            for (int j = 0; j < 4; j++) {
                acc[i][j] = fmaf(ai[i].x, aj[j].x, acc[i][j]);
                acc[i][j] = fmaf(ai[i].y, aj[j].y, acc[i][j]);
                acc[i][j] = fmaf(ai[i].z, aj[j].z, acc[i][j]);
                acc[i][j] = fmaf(ai[i].w, aj[j].w, acc[i][j]);
            }
    }

    float ps = 0.f, ns = 0.f;
#pragma unroll
    for (int i = 0; i < 4; i++)
#pragma unroll
        for (int j = 0; j < 4; j++) {
            int il = ty * 4 + i, jl = tx * 4 + j;
            int gi = i0 + il, gj = j0 + jl;
            float sq = sqi[il] + sqj[jl] - 2.f * acc[i][j];
            float d = (sq <= 0.f) ? 0.f : sqrtf(fmaxf(sq, 1e-16f));
            if (li[il] == lj[jl]) {
                if (gi != gj) ps += fmaxf(d - 0.7f, 0.f);
            } else {
                ns += fmaxf(1.4f - d, 0.f);
            }
        }

    red[tid] = ps; __syncthreads();
    for (int s = 128; s > 0; s >>= 1) { if (tid < s) red[tid] += red[tid + s]; __syncthreads(); }
    if (tid == 0) g_pos_part[by * 16 + bx] = red[0];
    __syncthreads();
    red[tid] = ns; __syncthreads();
    for (int s = 128; s > 0; s >>= 1) { if (tid < s) red[tid] += red[tid + s]; __syncthreads(); }
    if (tid == 0) g_neg_part[by * 16 + bx] = red[0];
}

__device__ __forceinline__ void loss_body(int blk, char* buf, const int* __restrict__ lb)
{
    float* red = (float*)buf;   // 32 B
    int w = threadIdx.x >> 5, lane = threadIdx.x & 31;
    int b = blk * 8 + w;
    int lbv = lb[b];
    int excl = (lbv < C_) ? lbv : -1;

    float v[5];
#pragma unroll
    for (int i = 0; i < 5; i++) {
        int c = lane + i * 32;
        v[i] = (c <= C_) ? g_logits[(long)c * B_ + b] : -1e30f;
    }
    float cand = -3e38f;
#pragma unroll
    for (int i = 0; i < 5; i++)
        if (lane + i * 32 == lbv) cand = v[i];
#pragma unroll
    for (int o = 16; o > 0; o >>= 1) cand = fmaxf(cand, __shfl_xor_sync(0xffffffffu, cand, o));
    float l_lb = cand;
    float l150 = __shfl_sync(0xffffffffu, v[4], 22);

    float m2 = -3e38f;
#pragma unroll
    for (int i = 0; i < 5; i++)
        m2 = fmaxf(m2, (lane + i * 32 == excl) ? -3e38f : v[i]);
#pragma unroll
    for (int o = 16; o > 0; o >>= 1) m2 = fmaxf(m2, __shfl_xor_sync(0xffffffffu, m2, o));

    float sum2 = 0.f;
#pragma unroll
    for (int i = 0; i < 5; i++)
        sum2 += (lane + i * 32 == excl) ? 0.f : expf(v[i] - m2);
#pragma unroll
    for (int o = 16; o > 0; o >>= 1) sum2 += __shfl_xor_sync(0xffffffffu, sum2, o);

    float loss2 = m2 + logf(sum2) - l150;
    float loss1 = 0.f;
    if (lbv < C_) {
        float m1 = fmaxf(l_lb, l150);
        loss1 = m1 + logf(expf(l_lb - m1) + expf(l150 - m1)) - l_lb;
    }
    if (lane == 0) red[w] = loss1 + loss2;
    __syncthreads();
    if (threadIdx.x == 0) {
        float s = 0.f;
#pragma unroll
        for (int i = 0; i < 8; i++) s += red[i];
        g_cls_part[blk] = s;
    }
}

__global__ __launch_bounds__(256)
void fusedC(const int* __restrict__ lb)
{
    __shared__ __align__(16) char buf[36864];
    int blk = blockIdx.x;
    if (blk < 256) pair_body(blk & 15, blk >> 4, buf, lb);
    else           loss_body(blk - 256, buf, lb);
}

// ---------------- final combine ----------------
__global__ void final_kernel(const int* __restrict__ lb, float* __restrict__ out)
{
    __shared__ float rp[256], rn[256], cl[256];
    __shared__ int hist[151];
    __shared__ int sq[256];
    int tid = threadIdx.x;
    rp[tid] = g_pos_part[tid];
    rn[tid] = g_neg_part[tid];
    cl[tid] = (tid < 128) ? g_cls_part[tid] : 0.f;
    if (tid < 151) hist[tid] = 0;
    __syncthreads();
    for (int b = tid; b < B_; b += 256) atomicAdd(&hist[lb[b]], 1);
    __syncthreads();
    sq[tid] = (tid < 151) ? hist[tid] * hist[tid] : 0;
    __syncthreads();
    for (int s = 128; s > 0; s >>= 1) {
        if (tid < s) {
            rp[tid] += rp[tid + s]; rn[tid] += rn[tid + s];
            sq[tid] += sq[tid + s]; cl[tid] += cl[tid + s];
        }
        __syncthreads();
    }
    if (tid == 0) {
        int ssq = sq[0];
        float pos_cnt = (float)(ssq - B_);
        float neg_cnt = (float)(B_ * B_ - ssq);
        out[0] = cl[0] / (float)B_
               + rp[0] / fmaxf(pos_cnt, 1.f)
               + rn[0] / fmaxf(neg_cnt, 1.f);
    }
}

// ---------------- launch (6 kernels) ----------------
extern "C" void kernel_launch(void* const* d_in, const int* in_sizes, int n_in,
                              void* d_out, int out_size)
{
    const float* x    = (const float*)d_in[0];
    const int*   lb   = (const int*)  d_in[1];
    const float* mem  = (const float*)d_in[2];
    const float* fc_w = (const float*)d_in[3];
    const float* fc_b = (const float*)d_in[4];
    const float* p1_w = (const float*)d_in[5];
    const float* p1_b = (const float*)d_in[6];
    const float* p2_w = (const float*)d_in[7];
    const float* p2_b = (const float*)d_in[8];
    float* out = (float*)d_out;

    float *xhT, *mhT;
    cudaGetSymbolAddress((void**)&xhT, g_xhT);
    cudaGetSymbolAddress((void**)&mhT, g_mhT);

    cudaFuncSetAttribute(gemm_mma, cudaFuncAttributeMaxDynamicSharedMemorySize, SMEM_MMA);

    long convItems = (long)TD * 192 + (long)B_ * 192 + 256L * 192;
    conv_kernel<<<(unsigned)((convItems + 255) / 256), 256>>>(x, mem, fc_w);
    gemm_mma<<<dim3(8, 12, 2), 256, SMEM_MMA>>>(fc_b);
    fusedA<<<512, 256>>>(xhT, mhT, p1_w, p2_w);
    fusedB<<<732, 256>>>(p1_b, p2_b);
    fusedC<<<384, 256>>>(lb);
    final_kernel<<<1, 256>>>(lb, out);
}

// round 13
// speedup vs baseline: 1.0533x; 1.0533x over previous
#include <cuda_runtime.h>
#include <cuda_bf16.h>
#include <math.h>
#include <cstdint>

#define B_    1024
#define D_    768
#define TD    1536
#define C_    150
#define CP    160
#define P_    64
#define K3    2304   // 3 * 768 packed bf16 K
#define USLAB 16     // u-GEMM k-split slabs

typedef unsigned long long u64;

#define PK2(d, lo, hi) asm("mov.b64 %0, {%1,%2};" : "=l"(d) : "f"(lo), "f"(hi))
#define UPK2(lo, hi, s) asm("mov.b64 {%0,%1}, %2;" : "=f"(lo), "=f"(hi) : "l"(s))
#define FMA2(d, a, b, c) asm("fma.rn.f32x2 %0, %1, %2, %3;" : "=l"(d) : "l"(a), "l"(b), "l"(c))
#define ADD2(d, a, b) asm("add.rn.f32x2 %0, %1, %2;" : "=l"(d) : "l"(a), "l"(b))

// ---------------- scratch (device globals; no allocation) ----------------
__device__ __align__(16) __nv_bfloat16 g_WxP[TD * K3];    // A-side: hi|hi|lo
__device__ __align__(16) __nv_bfloat16 g_WmP[TD * K3];
__device__ __align__(16) __nv_bfloat16 g_xP[B_ * K3];     // B-side: hi|lo|hi
__device__ __align__(16) __nv_bfloat16 g_memP[256 * K3];  // rows 150..255 zero
__device__ float g_xhT[TD * B_];              // xh transposed: [e][b] (+bias)
__device__ float g_mhT[TD * CP];              // [j][c], cols 150..159 zero
__device__ float g_seen_part[8][CP * B_];
__device__ float g_logits[CP * B_];
__device__ float g_u_part[USLAB][B_ * P_];
__device__ float g_u[B_ * P_];
__device__ float g_sqn[B_];
__device__ float g_pos_part[256];
__device__ float g_neg_part[256];
__device__ float g_cls_part[128];

// ---------------- small PTX helpers (all plain-sm_103-legal) ----------------
__device__ __forceinline__ uint32_t smem_u32(const void* p) {
    uint32_t a;
    asm("{ .reg .u64 t; cvta.to.shared.u64 t, %1; cvt.u32.u64 %0, t; }" : "=r"(a) : "l"(p));
    return a;
}
__device__ __forceinline__ void cp_async16(uint32_t sm, const void* g) {
    asm volatile("cp.async.cg.shared.global [%0], [%1], 16;" :: "r"(sm), "l"(g));
}
#define CP_COMMIT() asm volatile("cp.async.commit_group;")
#define CP_WAIT(n)  asm volatile("cp.async.wait_group %0;" :: "n"(n))
__device__ __forceinline__ void ldm4(uint32_t* r, uint32_t addr) {
    asm volatile("ldmatrix.sync.aligned.m8n8.x4.shared.b16 {%0,%1,%2,%3}, [%4];"
                 : "=r"(r[0]), "=r"(r[1]), "=r"(r[2]), "=r"(r[3]) : "r"(addr));
}
__device__ __forceinline__ void mma16816(float* c, const uint32_t* a, uint32_t b0, uint32_t b1) {
    asm volatile("mma.sync.aligned.m16n8k16.row.col.f32.bf16.bf16.f32 "
                 "{%0,%1,%2,%3}, {%4,%5,%6,%7}, {%8,%9}, {%0,%1,%2,%3};"
                 : "+f"(c[0]), "+f"(c[1]), "+f"(c[2]), "+f"(c[3])
                 : "r"(a[0]), "r"(a[1]), "r"(a[2]), "r"(a[3]), "r"(b0), "r"(b1));
}

// ---------------- fused hi/lo bf16 convert ----------------
__device__ __forceinline__ uint32_t pk_bf2(__nv_bfloat16 a, __nv_bfloat16 b) {
    __nv_bfloat162 t(a, b);
    return *reinterpret_cast<uint32_t*>(&t);
}
__device__ __forceinline__ void hilo4(float4 v, uint2& hi, uint2& lo) {
    __nv_bfloat16 h0 = __float2bfloat16(v.x), h1 = __float2bfloat16(v.y);
    __nv_bfloat16 h2 = __float2bfloat16(v.z), h3 = __float2bfloat16(v.w);
    __nv_bfloat16 l0 = __float2bfloat16(v.x - __bfloat162float(h0));
    __nv_bfloat16 l1 = __float2bfloat16(v.y - __bfloat162float(h1));
    __nv_bfloat16 l2 = __float2bfloat16(v.z - __bfloat162float(h2));
    __nv_bfloat16 l3 = __float2bfloat16(v.w - __bfloat162float(h3));
    hi.x = pk_bf2(h0, h1); hi.y = pk_bf2(h2, h3);
    lo.x = pk_bf2(l0, l1); lo.y = pk_bf2(l2, l3);
}
__global__ void conv_kernel(const float* __restrict__ x, const float* __restrict__ mem,
                            const float* __restrict__ fcw)
{
    const long NW = (long)TD * 192, NX = (long)B_ * 192, NM = 256L * 192;
    long gid = (long)blockIdx.x * 256 + threadIdx.x;
    if (gid < NW) {
        int r = (int)(gid / 192), k4 = (int)(gid % 192) * 4;
        float4 vx = *(const float4*)&fcw[(long)r * TD + k4];
        float4 vm = *(const float4*)&fcw[(long)r * TD + D_ + k4];
        uint2 hx, lx, hm, lm;
        hilo4(vx, hx, lx); hilo4(vm, hm, lm);
        *(uint2*)&g_WxP[(long)r * K3 + k4]            = hx;
        *(uint2*)&g_WxP[(long)r * K3 + D_ + k4]       = hx;
        *(uint2*)&g_WxP[(long)r * K3 + 2 * D_ + k4]   = lx;
        *(uint2*)&g_WmP[(long)r * K3 + k4]            = hm;
        *(uint2*)&g_WmP[(long)r * K3 + D_ + k4]       = hm;
        *(uint2*)&g_WmP[(long)r * K3 + 2 * D_ + k4]   = lm;
    } else if (gid < NW + NX) {
        long t = gid - NW;
        int r = (int)(t / 192), k4 = (int)(t % 192) * 4;
        float4 v = *(const float4*)&x[(long)r * D_ + k4];
        uint2 h, l; hilo4(v, h, l);
        *(uint2*)&g_xP[(long)r * K3 + k4]          = h;
        *(uint2*)&g_xP[(long)r * K3 + D_ + k4]     = l;
        *(uint2*)&g_xP[(long)r * K3 + 2 * D_ + k4] = h;
    } else if (gid < NW + NX + NM) {
        long t = gid - NW - NX;
        int r = (int)(t / 192), k4 = (int)(t % 192) * 4;
        uint2 h = make_uint2(0u, 0u), l = make_uint2(0u, 0u);
        if (r < C_) {
            float4 v = *(const float4*)&mem[(long)r * D_ + k4];
            hilo4(v, h, l);
        }
        *(uint2*)&g_memP[(long)r * K3 + k4]          = h;
        *(uint2*)&g_memP[(long)r * K3 + D_ + k4]     = l;
        *(uint2*)&g_memP[(long)r * K3 + 2 * D_ + k4] = h;
    }
}

// ---------------- mma.sync bf16 GEMM, 128x128 tile, cp.async double-buffered ----
#define ST_BYTES 36864
#define SMEM_MMA (2 * ST_BYTES)
#define PITCH    144

__global__ __launch_bounds__(256)
void gemm_mma(const float* __restrict__ fc_b)
{
    bool isX = (blockIdx.z == 0);
    if (!isX && blockIdx.x >= 2) return;
    extern __shared__ char smem[];
    const char* A  = (const char*)(isX ? g_WxP : g_WmP);
    const char* Bm = (const char*)(isX ? g_xP : g_memP);
    float* Out = isX ? g_xhT : g_mhT;
    int ldo = isX ? B_ : CP;
    int m0 = blockIdx.y * 128, n0 = blockIdx.x * 128;
    const long ROWB = (long)K3 * 2;

    int tid = threadIdx.x, lane = tid & 31, wid = tid >> 5;
    int wm = wid & 3, wn = wid >> 2;
    uint32_t sb = smem_u32(smem);

    float acc[2][8][4];
#pragma unroll
    for (int f = 0; f < 2; f++)
#pragma unroll
        for (int g = 0; g < 8; g++)
#pragma unroll
            for (int q = 0; q < 4; q++) acc[f][g][q] = 0.f;

    int lrow = tid >> 3, lc = (tid & 7) * 16;

#define STAGE_LOAD(ci, s) do { \
        uint32_t ao = sb + (s) * ST_BYTES, bo = ao + 18432; \
        long kb = (long)(ci) * 128; \
        cp_async16(ao + lrow * PITCH + lc,        A  + (long)(m0 + lrow) * ROWB + kb + lc); \
        cp_async16(ao + (lrow + 32) * PITCH + lc, A  + (long)(m0 + lrow + 32) * ROWB + kb + lc); \
        cp_async16(ao + (lrow + 64) * PITCH + lc, A  + (long)(m0 + lrow + 64) * ROWB + kb + lc); \
        cp_async16(ao + (lrow + 96) * PITCH + lc, A  + (long)(m0 + lrow + 96) * ROWB + kb + lc); \
        cp_async16(bo + lrow * PITCH + lc,        Bm + (long)(n0 + lrow) * ROWB + kb + lc); \
        cp_async16(bo + (lrow + 32) * PITCH + lc, Bm + (long)(n0 + lrow + 32) * ROWB + kb + lc); \
        cp_async16(bo + (lrow + 64) * PITCH + lc, Bm + (long)(n0 + lrow + 64) * ROWB + kb + lc); \
        cp_async16(bo + (lrow + 96) * PITCH + lc, Bm + (long)(n0 + lrow + 96) * ROWB + kb + lc); \
        CP_COMMIT(); \
    } while (0)

    STAGE_LOAD(0, 0);

    uint32_t aRow = (uint32_t)(wm * 32 + (lane & 15)) * PITCH + ((lane >> 4) & 1) * 16;
    uint32_t bRowBase = (uint32_t)(wn * 64 + (lane & 7)) * PITCH + (lane >> 3) * 16;

    for (int ci = 0; ci < 36; ci++) {
        int s = ci & 1;
        if (ci + 1 < 36) STAGE_LOAD(ci + 1, s ^ 1);
        if (ci + 1 < 36) CP_WAIT(1); else CP_WAIT(0);
        __syncthreads();
        uint32_t ao = sb + s * ST_BYTES, bo = ao + 18432;
#pragma unroll
        for (int h = 0; h < 2; h++) {
            uint32_t bfr[8][4];
#pragma unroll
            for (int g = 0; g < 8; g++)
                ldm4(bfr[g], bo + bRowBase + g * 8 * PITCH + h * 64);
#pragma unroll
            for (int ks = 0; ks < 2; ks++) {
                uint32_t afr[2][4];
#pragma unroll
                for (int f = 0; f < 2; f++)
                    ldm4(afr[f], ao + aRow + f * 16 * PITCH + h * 64 + ks * 32);
#pragma unroll
                for (int f = 0; f < 2; f++)
#pragma unroll
                    for (int g = 0; g < 8; g++)
                        mma16816(acc[f][g], afr[f], bfr[g][2 * ks], bfr[g][2 * ks + 1]);
            }
        }
        __syncthreads();
    }

    int gid = lane >> 2, tig = lane & 3;
#pragma unroll
    for (int f = 0; f < 2; f++) {
        int m = m0 + wm * 32 + f * 16 + gid;
        float b0 = isX ? fc_b[m] : 0.f;
        float b1 = isX ? fc_b[m + 8] : 0.f;
        float* r0 = Out + (long)m * ldo;
        float* r1 = Out + (long)(m + 8) * ldo;
#pragma unroll
        for (int g = 0; g < 8; g++) {
            int n = n0 + wn * 64 + g * 8 + 2 * tig;
            if (n < ldo) {
                *(float2*)&r0[n] = make_float2(acc[f][g][0] + b0, acc[f][g][1] + b0);
                *(float2*)&r1[n] = make_float2(acc[f][g][2] + b1, acc[f][g][3] + b1);
            }
        }
    }
}

// ---------------- seen kernel (round-11 proven form, separate launch) --------
__global__ __launch_bounds__(256)
void seen_kernel(const float* __restrict__ xhT, const float* __restrict__ mhT,
                 const float* __restrict__ p1w)
{
    __shared__ float xs[32][36];
    __shared__ u64 ms2[32][160];
    __shared__ float ps[32];
    int tid = threadIdx.x;
    int tx = tid & 31, ty = tid >> 5;
    int bbase = blockIdx.x * 32;
    int c0 = tx * 5;

    u64 acc0[5], acc1[5];
#pragma unroll
    for (int j = 0; j < 5; j++) { acc0[j] = 0ull; acc1[j] = 0ull; }

    for (int et = 0; et < 6; et++) {
        int eb = blockIdx.y * 192 + et * 32;
        {
            int el = tid >> 3, b4 = (tid & 7) * 4;
            *(float4*)&xs[el][b4] = *(const float4*)&xhT[(long)(eb + el) * B_ + bbase + b4];
        }
        {
            int el = tid >> 3, cf = (tid & 7) * 20;
#pragma unroll
            for (int q = 0; q < 5; q++) {
                float4 v = *(const float4*)&mhT[(long)(eb + el) * CP + cf + q * 4];
                PK2(ms2[el][cf + q * 4 + 0], v.x, v.x);
                PK2(ms2[el][cf + q * 4 + 1], v.y, v.y);
                PK2(ms2[el][cf + q * 4 + 2], v.z, v.z);
                PK2(ms2[el][cf + q * 4 + 3], v.w, v.w);
            }
        }
        if (tid < 8) *(float4*)&ps[tid * 4] = *(const float4*)&p1w[eb + tid * 4];
        __syncthreads();
#pragma unroll 4
        for (int ee = 0; ee < 32; ee++) {
            float p = ps[ee];
            u64 pp; PK2(pp, p, p);
            u64 x01 = *(u64*)&xs[ee][ty * 4];
            u64 x23 = *(u64*)&xs[ee][ty * 4 + 2];
#pragma unroll
            for (int j = 0; j < 5; j++) {
                u64 mm = ms2[ee][c0 + j];
                u64 t0, t1;
                ADD2(t0, x01, mm);
                ADD2(t1, x23, mm);
                float a, b, c, d;
                UPK2(a, b, t0); UPK2(c, d, t1);
                a = fmaxf(a, 0.f); b = fmaxf(b, 0.f);
                c = fmaxf(c, 0.f); d = fmaxf(d, 0.f);
                u64 r0, r1; PK2(r0, a, b); PK2(r1, c, d);
                FMA2(acc0[j], r0, pp, acc0[j]);
                FMA2(acc1[j], r1, pp, acc1[j]);
            }
        }
        __syncthreads();
    }
#pragma unroll
    for (int j = 0; j < 5; j++) {
        float v0, v1, v2, v3;
        UPK2(v0, v1, acc0[j]); UPK2(v2, v3, acc1[j]);
        *(float4*)&g_seen_part[blockIdx.y][(long)(c0 + j) * B_ + bbase + ty * 4] =
            make_float4(v0, v1, v2, v3);
    }
}

// ---------------- GEMM 64x64, A k-major with relu (round-11 form) ------------
__global__ __launch_bounds__(256)
void gemm64x64_reluAT(const float* __restrict__ A, int lda,
                      const float* __restrict__ Bm, int ldb,
                      float* __restrict__ Out, int ldo, long slabStride,
                      int N, int kc)
{
    __shared__ float As[16][68];
    __shared__ float Bs[16][68];
    int tid = threadIdx.x;
    int tx = tid & 15, ty = tid >> 4;
    int m0 = blockIdx.y * 64, n0 = blockIdx.x * 64;
    int kb0 = blockIdx.z * kc, kb1 = kb0 + kc;
    Out += (long)blockIdx.z * slabStride;

    float acc[4][4];
#pragma unroll
    for (int i = 0; i < 4; i++)
#pragma unroll
        for (int j = 0; j < 4; j++) acc[i][j] = 0.f;

    for (int kb = kb0; kb < kb1; kb += 16) {
        {
            int kl = tid >> 4, m4 = (tid & 15) * 4;
            float4 v = *(const float4*)&A[(long)(kb + kl) * lda + m0 + m4];
            As[kl][m4 + 0] = fmaxf(v.x, 0.f);
            As[kl][m4 + 1] = fmaxf(v.y, 0.f);
            As[kl][m4 + 2] = fmaxf(v.z, 0.f);
            As[kl][m4 + 3] = fmaxf(v.w, 0.f);
        }
        {
            int nl = tid >> 2, k4 = (tid & 3) * 4;
            float4 v = make_float4(0.f, 0.f, 0.f, 0.f);
            if (n0 + nl < N)
                v = *(const float4*)&Bm[(long)(n0 + nl) * ldb + kb + k4];
            Bs[k4 + 0][nl] = v.x; Bs[k4 + 1][nl] = v.y;
            Bs[k4 + 2][nl] = v.z; Bs[k4 + 3][nl] = v.w;
        }
        __syncthreads();
#pragma unroll
        for (int kk = 0; kk < 16; kk++) {
            float4 a = *(float4*)&As[kk][ty * 4];
            float4 b = *(float4*)&Bs[kk][tx * 4];
            float av[4] = {a.x, a.y, a.z, a.w};
            float bv[4] = {b.x, b.y, b.z, b.w};
#pragma unroll
            for (int i = 0; i < 4; i++)
#pragma unroll
                for (int j = 0; j < 4; j++) acc[i][j] = fmaf(av[i], bv[j], acc[i][j]);
        }
        __syncthreads();
    }
#pragma unroll
    for (int i = 0; i < 4; i++) {
        int m = m0 + ty * 4 + i;
#pragma unroll
        for (int j = 0; j < 4; j++) {
            int n = n0 + tx * 4 + j;
            if (n < N) Out[(long)m * ldo + n] = acc[i][j];
        }
    }
}

// ============ fused stage B: logits (0..603) | u_norm (604..731) =============
__global__ __launch_bounds__(256)
void fusedB(const float* __restrict__ p1b, const float* __restrict__ p2b)
{
    int blk = blockIdx.x;
    if (blk < 604) {
        int idx = blk * 256 + threadIdx.x;
        if (idx >= (C_ + 1) * B_) return;
        float v = p1b[0];
#pragma unroll
        for (int s = 0; s < 8; s++) v += g_seen_part[s][idx];
        g_logits[idx] = v;
    } else {
        int wid = threadIdx.x >> 5, lane = threadIdx.x & 31;
        int b = (blk - 604) * 8 + wid;
        float v0 = p2b[lane], v1 = p2b[lane + 32];
#pragma unroll
        for (int s = 0; s < USLAB; s++) {
            v0 += g_u_part[s][b * P_ + lane];
            v1 += g_u_part[s][b * P_ + lane + 32];
        }
        float ss = v0 * v0 + v1 * v1;
#pragma unroll
        for (int o = 16; o > 0; o >>= 1) ss += __shfl_xor_sync(0xffffffffu, ss, o);
        float den = fmaxf(sqrtf(ss), 1e-12f);
        float w0 = v0 / den, w1 = v1 / den;
        g_u[b * P_ + lane] = w0;
        g_u[b * P_ + lane + 32] = w1;
        float s2 = w0 * w0 + w1 * w1;
#pragma unroll
        for (int o = 16; o > 0; o >>= 1) s2 += __shfl_xor_sync(0xffffffffu, s2, o);
        if (lane == 0) g_sqn[b] = s2;
    }
}

// ============ fused stage C: pair (0..255) | loss (256..383) =================
__device__ __forceinline__ void pair_body(int bx, int by, char* buf,
                                          const int* __restrict__ lb)
{
    float (*ui)[68] = (float(*)[68])buf;               // 17408
    float (*uj)[68] = (float(*)[68])(buf + 17408);     // 17408
    float* red = (float*)(buf + 34816);                // 1024
    float* sqi = (float*)(buf + 35840);                // 256
    float* sqj = (float*)(buf + 36096);                // 256
    int*   li  = (int*)  (buf + 36352);                // 256
    int*   lj  = (int*)  (buf + 36608);                // 256
    int tid = threadIdx.x;
    int tx = tid & 15, ty = tid >> 4;
    int i0 = by * 64, j0 = bx * 64;

#pragma unroll
    for (int t = 0; t < 4; t++) {
        int f4 = tid + t * 256;
        int r = f4 >> 4, k4 = (f4 & 15) * 4;
        *(float4*)&ui[r][k4] = *(const float4*)&g_u[(i0 + r) * P_ + k4];
        *(float4*)&uj[r][k4] = *(const float4*)&g_u[(j0 + r) * P_ + k4];
    }
    if (tid < 64) {
        sqi[tid] = g_sqn[i0 + tid]; sqj[tid] = g_sqn[j0 + tid];
        li[tid] = lb[i0 + tid];     lj[tid] = lb[j0 + tid];
    }
    __syncthreads();

    float acc[4][4];
#pragma unroll
    for (int i = 0; i < 4; i++)
#pragma unroll
        for (int j = 0; j < 4; j++) acc[i][j] = 0.f;

#pragma unroll
    for (int k4 = 0; k4 < 16; k4++) {
        float4 ai[4], aj[4];
#pragma unroll
        for (int i = 0; i < 4; i++) ai[i] = *(float4*)&ui[ty * 4 + i][k4 * 4];
#pragma unroll
        for (int j = 0; j < 4; j++) aj[j] = *(float4*)&uj[tx * 4 + j][k4 * 4];
#pragma unroll
        for (int i = 0; i < 4; i++)
#pragma unroll
            for (int j = 0; j < 4; j++) {
                acc[i][j] = fmaf(ai[i].x, aj[j].x, acc[i][j]);
                acc[i][j] = fmaf(ai[i].y, aj[j].y, acc[i][j]);
                acc[i][j] = fmaf(ai[i].z, aj[j].z, acc[i][j]);
                acc[i][j] = fmaf(ai[i].w, aj[j].w, acc[i][j]);
            }
    }

    float ps = 0.f, ns = 0.f;
#pragma unroll
    for (int i = 0; i < 4; i++)
#pragma unroll
        for (int j = 0; j < 4; j++) {
            int il = ty * 4 + i, jl = tx * 4 + j;
            int gi = i0 + il, gj = j0 + jl;
            float sq = sqi[il] + sqj[jl] - 2.f * acc[i][j];
            float d = (sq <= 0.f) ? 0.f : sqrtf(fmaxf(sq, 1e-16f));
            if (li[il] == lj[jl]) {
                if (gi != gj) ps += fmaxf(d - 0.7f, 0.f);
            } else {
                ns += fmaxf(1.4f - d, 0.f);
            }
        }

    red[tid] = ps; __syncthreads();
    for (int s = 128; s > 0; s >>= 1) { if (tid < s) red[tid] += red[tid + s]; __syncthreads(); }
    if (tid == 0) g_pos_part[by * 16 + bx] = red[0];
    __syncthreads();
    red[tid] = ns; __syncthreads();
    for (int s = 128; s > 0; s >>= 1) { if (tid < s) red[tid] += red[tid + s]; __syncthreads(); }
    if (tid == 0) g_neg_part[by * 16 + bx] = red[0];
}

__device__ __forceinline__ void loss_body(int blk, char* buf, const int* __restrict__ lb)
{
    float* red = (float*)buf;
    int w = threadIdx.x >> 5, lane = threadIdx.x & 31;
    int b = blk * 8 + w;
    int lbv = lb[b];
    int excl = (lbv < C_) ? lbv : -1;

    float v[5];
#pragma unroll
    for (int i = 0; i < 5; i++) {
        int c = lane + i * 32;
        v[i] = (c <= C_) ? g_logits[(long)c * B_ + b] : -1e30f;
    }
    float cand = -3e38f;
#pragma unroll
    for (int i = 0; i < 5; i++)
        if (lane + i * 32 == lbv) cand = v[i];
#pragma unroll
    for (int o = 16; o > 0; o >>= 1) cand = fmaxf(cand, __shfl_xor_sync(0xffffffffu, cand, o));
    float l_lb = cand;
    float l150 = __shfl_sync(0xffffffffu, v[4], 22);

    float m2 = -3e38f;
#pragma unroll
    for (int i = 0; i < 5; i++)
        m2 = fmaxf(m2, (lane + i * 32 == excl) ? -3e38f : v[i]);
#pragma unroll
    for (int o = 16; o > 0; o >>= 1) m2 = fmaxf(m2, __shfl_xor_sync(0xffffffffu, m2, o));

    float sum2 = 0.f;
#pragma unroll
    for (int i = 0; i < 5; i++)
        sum2 += (lane + i * 32 == excl) ? 0.f : expf(v[i] - m2);
#pragma unroll
    for (int o = 16; o > 0; o >>= 1) sum2 += __shfl_xor_sync(0xffffffffu, sum2, o);

    float loss2 = m2 + logf(sum2) - l150;
    float loss1 = 0.f;
    if (lbv < C_) {
        float m1 = fmaxf(l_lb, l150);
        loss1 = m1 + logf(expf(l_lb - m1) + expf(l150 - m1)) - l_lb;
    }
    if (lane == 0) red[w] = loss1 + loss2;
    __syncthreads();
    if (threadIdx.x == 0) {
        float s = 0.f;
#pragma unroll
        for (int i = 0; i < 8; i++) s += red[i];
        g_cls_part[blk] = s;
    }
}

__global__ __launch_bounds__(256)
void fusedC(const int* __restrict__ lb)
{
    __shared__ __align__(16) char buf[36864];
    int blk = blockIdx.x;
    if (blk < 256) pair_body(blk & 15, blk >> 4, buf, lb);
    else           loss_body(blk - 256, buf, lb);
}

// ---------------- final combine ----------------
__global__ void final_kernel(const int* __restrict__ lb, float* __restrict__ out)
{
    __shared__ float rp[256], rn[256], cl[256];
    __shared__ int hist[151];
    __shared__ int sq[256];
    int tid = threadIdx.x;
    rp[tid] = g_pos_part[tid];
    rn[tid] = g_neg_part[tid];
    cl[tid] = (tid < 128) ? g_cls_part[tid] : 0.f;
    if (tid < 151) hist[tid] = 0;
    __syncthreads();
    for (int b = tid; b < B_; b += 256) atomicAdd(&hist[lb[b]], 1);
    __syncthreads();
    sq[tid] = (tid < 151) ? hist[tid] * hist[tid] : 0;
    __syncthreads();
    for (int s = 128; s > 0; s >>= 1) {
        if (tid < s) {
            rp[tid] += rp[tid + s]; rn[tid] += rn[tid + s];
            sq[tid] += sq[tid + s]; cl[tid] += cl[tid + s];
        }
        __syncthreads();
    }
    if (tid == 0) {
        int ssq = sq[0];
        float pos_cnt = (float)(ssq - B_);
        float neg_cnt = (float)(B_ * B_ - ssq);
        out[0] = cl[0] / (float)B_
               + rp[0] / fmaxf(pos_cnt, 1.f)
               + rn[0] / fmaxf(neg_cnt, 1.f);
    }
}

// ---------------- launch (7 kernels: R11 front + fused B/C tail) -------------
extern "C" void kernel_launch(void* const* d_in, const int* in_sizes, int n_in,
                              void* d_out, int out_size)
{
    const float* x    = (const float*)d_in[0];
    const int*   lb   = (const int*)  d_in[1];
    const float* mem  = (const float*)d_in[2];
    const float* fc_w = (const float*)d_in[3];
    const float* fc_b = (const float*)d_in[4];
    const float* p1_w = (const float*)d_in[5];
    const float* p1_b = (const float*)d_in[6];
    const float* p2_w = (const float*)d_in[7];
    const float* p2_b = (const float*)d_in[8];
    float* out = (float*)d_out;

    float *xhT, *mhT, *u_part;
    cudaGetSymbolAddress((void**)&xhT, g_xhT);
    cudaGetSymbolAddress((void**)&mhT, g_mhT);
    cudaGetSymbolAddress((void**)&u_part, g_u_part);

    cudaFuncSetAttribute(gemm_mma, cudaFuncAttributeMaxDynamicSharedMemorySize, SMEM_MMA);

    long convItems = (long)TD * 192 + (long)B_ * 192 + 256L * 192;
    conv_kernel<<<(unsigned)((convItems + 255) / 256), 256>>>(x, mem, fc_w);
    gemm_mma<<<dim3(8, 12, 2), 256, SMEM_MMA>>>(fc_b);
    seen_kernel<<<dim3(32, 8), 256>>>(xhT, mhT, p1_w);
    gemm64x64_reluAT<<<dim3(1, 16, USLAB), 256>>>(xhT, B_, p2_w, TD,
                                                  u_part, P_, (long)B_ * P_, P_, TD / USLAB);
    fusedB<<<732, 256>>>(p1_b, p2_b);
    fusedC<<<384, 256>>>(lb);
    final_kernel<<<1, 256>>>(lb, out);
}